// round 3
// baseline (speedup 1.0000x reference)
#include <cuda_runtime.h>
#include <math_constants.h>

#define B_      4
#define N_      16384
#define STRIDE_ 4
#define K_      20
#define D_      64
#define DK_     67
#define KFS_    68
#define M_      4096
#define NQ_     (B_*M_)     // 16384
#define HID_    128
#define OUT_    128
#define TK_     128         // keys per tile
#define QW_     8           // queries per warp
#define KNT_    512         // knn threads / block
#define QB_     128         // queries per block (16 warps * 8)

typedef unsigned long long u64_t;

__device__ __forceinline__ u64_t fma2_(u64_t a, u64_t b, u64_t c) {
    u64_t d; asm("fma.rn.f32x2 %0,%1,%2,%3;" : "=l"(d) : "l"(a), "l"(b), "l"(c)); return d;
}
__device__ __forceinline__ u64_t add2_(u64_t a, u64_t b) {
    u64_t d; asm("add.rn.f32x2 %0,%1,%2;" : "=l"(d) : "l"(a), "l"(b)); return d;
}
__device__ __forceinline__ u64_t pack2_(float x, float y) {
    u64_t r; asm("mov.b64 %0,{%1,%2};" : "=l"(r) : "f"(x), "f"(y)); return r;
}
__device__ __forceinline__ float2 unpk2_(u64_t v) {
    float x, y; asm("mov.b64 {%0,%1},%2;" : "=f"(x), "=f"(y) : "l"(v)); return make_float2(x, y);
}

// scratch (no cudaMalloc allowed)
__device__ float g_kf[(size_t)B_*N_*KFS_];   // transformed features (padded rows, pad=0)
__device__ float g_kn[B_*N_];                // key squared norms
__device__ int   g_nbr[NQ_*K_];              // global neighbor indices

// ---------------------------------------------------------------------------
// Kernel 1: per-point transform -> kf, norms, and passthrough outputs
// ---------------------------------------------------------------------------
__global__ void __launch_bounds__(256) k_prep(const float* __restrict__ x,
                                              const float* __restrict__ pos,
                                              const float* __restrict__ lfr,
                                              float* __restrict__ outp,
                                              int out_size)
{
    int n = blockIdx.x * blockDim.x + threadIdx.x;
    if (n >= B_*N_) return;
    const float* xr = x + (size_t)n * D_;
    const float* R  = lfr + (size_t)n * 9;
    float r[9];
#pragma unroll
    for (int i = 0; i < 9; i++) r[i] = R[i];

    float kf[DK_];
#pragma unroll
    for (int i = 0; i < 16; i++) kf[i] = xr[i];
#pragma unroll
    for (int v = 0; v < 16; v++) {
        float b0 = xr[16+3*v+0], b1 = xr[16+3*v+1], b2 = xr[16+3*v+2];
#pragma unroll
        for (int a = 0; a < 3; a++)
            kf[16+3*v+a] = r[0*3+a]*b0 + r[1*3+a]*b1 + r[2*3+a]*b2;
    }
    float p0 = pos[n*3+0], p1 = pos[n*3+1], p2 = pos[n*3+2];
    kf[64] = p0; kf[65] = p1; kf[66] = p2;

    float s = 0.f;
#pragma unroll
    for (int i = 0; i < DK_; i++) { g_kf[(size_t)n*KFS_ + i] = kf[i]; s += kf[i]*kf[i]; }
    g_kf[(size_t)n*KFS_ + 67] = 0.f;
    g_kn[n] = s;

    if ((n & 3) == 0) {
        int b   = n >> 14;
        int qid = b*M_ + ((n & (N_-1)) >> 2);
        const int off_pos = NQ_*OUT_;
        const int off_bat = off_pos + NQ_*3;
        const int off_lf  = off_bat + NQ_;
        if (out_size >= off_lf + NQ_*9) {
            float* pos_out = outp + off_pos;
            float* bat_out = outp + off_bat;
            float* lf_out  = outp + off_lf;
            pos_out[qid*3+0] = p0; pos_out[qid*3+1] = p1; pos_out[qid*3+2] = p2;
            bat_out[qid] = (float)b;
#pragma unroll
            for (int i = 0; i < 9; i++) lf_out[qid*9+i] = r[i];
        }
    }
}

// ---------------------------------------------------------------------------
// Warp-distributed top-K insert (lanes 0..19 hold kept entries)
// ---------------------------------------------------------------------------
__device__ __forceinline__ void topk_insert(float d2, int gidx,
                                            float& kd, int& ki, float& th, int lane)
{
    unsigned m = __ballot_sync(0xffffffffu, d2 < th);
    while (m) {
        int src = __ffs(m) - 1; m &= m - 1;
        float v  = __shfl_sync(0xffffffffu, d2,  src);
        int   vi = __shfl_sync(0xffffffffu, gidx, src);
        if (v < th) {
            float mx = kd; int ml = lane;
#pragma unroll
            for (int off = 16; off; off >>= 1) {
                float om = __shfl_xor_sync(0xffffffffu, mx, off);
                int   ol = __shfl_xor_sync(0xffffffffu, ml, off);
                if (om > mx || (om == mx && ol < ml)) { mx = om; ml = ol; }
            }
            if (lane == ml) { kd = v; ki = vi; }
            float t = kd;
#pragma unroll
            for (int off = 16; off; off >>= 1)
                t = fmaxf(t, __shfl_xor_sync(0xffffffffu, t, off));
            th = t;
        }
    }
}

// ---------------------------------------------------------------------------
// Kernel 2: exact KNN, f32x2 FMA. 512 thr = 16 warps; warp owns 8 queries.
// Double-buffered key tiles; one barrier per tile.
// ---------------------------------------------------------------------------
__global__ void __launch_bounds__(KNT_, 1) k_knn()
{
    extern __shared__ float smem[];
    float* kbuf0 = smem;                       // [TK_][17 float4]
    float* kbuf1 = smem + TK_*KFS_;
    float* knb   = smem + 2*TK_*KFS_;          // [2][TK_]
    float4* sq4  = (float4*)(smem + 2*TK_*KFS_ + 2*TK_);  // [QB_][17]

    const int tid = threadIdx.x, lane = tid & 31, w = tid >> 5;
    const int qbase = blockIdx.x * QB_;
    const int b = qbase >> 12;                 // 128 | 4096 -> same batch
    const int kb0 = b * N_;
    const float4* kf4 = (const float4*)g_kf;

    // stage 128 query rows
    for (int i = tid; i < QB_*17; i += KNT_) {
        int qq = i / 17, g = i - qq*17;
        int pt = kb0 + ((qbase + qq) - b*M_) * STRIDE_;
        sq4[i] = kf4[(size_t)pt*17 + g];
    }
    // stage tile 0
    {
        const float4* src = kf4 + (size_t)kb0*17;
        float4* dst = (float4*)kbuf0;
        for (int i = tid; i < TK_*17; i += KNT_) dst[i] = src[i];
        if (tid < TK_) knb[tid] = g_kn[kb0 + tid];
    }

    float kd[QW_], th[QW_];
    int   ki[QW_];
#pragma unroll
    for (int q = 0; q < QW_; q++) {
        kd[q] = (lane < K_) ? CUDART_INF_F : -CUDART_INF_F;
        ki[q] = 0;
        th[q] = CUDART_INF_F;
    }
    const ulonglong2* sq2w = (const ulonglong2*)(sq4 + (w*QW_)*17);

    __syncthreads();

    for (int tile = 0; tile < N_/TK_; tile++) {
        const int cur = tile & 1;
        const float* kb = cur ? kbuf1 : kbuf0;
        // prefetch next tile into other buffer
        if (tile + 1 < N_/TK_) {
            const float4* src = kf4 + (size_t)(kb0 + (tile+1)*TK_)*17;
            float4* dst = (float4*)(cur ? kbuf0 : kbuf1);
            for (int i = tid; i < TK_*17; i += KNT_) dst[i] = src[i];
            if (tid < TK_) knb[(cur^1)*TK_ + tid] = g_kn[kb0 + (tile+1)*TK_ + tid];
        }

        const ulonglong2* sk2 = (const ulonglong2*)kb;
        u64_t acc[QW_][4];
#pragma unroll
        for (int q = 0; q < QW_; q++) {
            acc[q][0] = 0ull; acc[q][1] = 0ull; acc[q][2] = 0ull; acc[q][3] = 0ull;
        }

#pragma unroll 1
        for (int g = 0; g < 17; g++) {
            ulonglong2 k0 = sk2[(lane      )*17 + g];
            ulonglong2 k1 = sk2[(lane +  32)*17 + g];
            ulonglong2 k2 = sk2[(lane +  64)*17 + g];
            ulonglong2 k3 = sk2[(lane +  96)*17 + g];
#pragma unroll
            for (int q = 0; q < QW_; q++) {
                ulonglong2 qv = sq2w[q*17 + g];     // broadcast LDS.128
                acc[q][0] = fma2_(qv.x, k0.x, acc[q][0]);
                acc[q][1] = fma2_(qv.x, k1.x, acc[q][1]);
                acc[q][2] = fma2_(qv.x, k2.x, acc[q][2]);
                acc[q][3] = fma2_(qv.x, k3.x, acc[q][3]);
                acc[q][0] = fma2_(qv.y, k0.y, acc[q][0]);
                acc[q][1] = fma2_(qv.y, k1.y, acc[q][1]);
                acc[q][2] = fma2_(qv.y, k2.y, acc[q][2]);
                acc[q][3] = fma2_(qv.y, k3.y, acc[q][3]);
            }
        }

        const float* kn = knb + cur*TK_;
        const float kn0 = kn[lane], kn1 = kn[lane+32], kn2 = kn[lane+64], kn3 = kn[lane+96];
        const int gi = kb0 + tile*TK_ + lane;
#pragma unroll
        for (int q = 0; q < QW_; q++) {
            float2 s0 = unpk2_(acc[q][0]);
            float2 s1 = unpk2_(acc[q][1]);
            float2 s2 = unpk2_(acc[q][2]);
            float2 s3 = unpk2_(acc[q][3]);
            float d2;
            d2 = kn0 - 2.f*(s0.x + s0.y); topk_insert(d2, gi,    kd[q], ki[q], th[q], lane);
            d2 = kn1 - 2.f*(s1.x + s1.y); topk_insert(d2, gi+32, kd[q], ki[q], th[q], lane);
            d2 = kn2 - 2.f*(s2.x + s2.y); topk_insert(d2, gi+64, kd[q], ki[q], th[q], lane);
            d2 = kn3 - 2.f*(s3.x + s3.y); topk_insert(d2, gi+96, kd[q], ki[q], th[q], lane);
        }
        __syncthreads();
    }

    if (lane < K_) {
#pragma unroll
        for (int q = 0; q < QW_; q++)
            g_nbr[(qbase + w*QW_ + q)*K_ + lane] = ki[q];
    }
}

// ---------------------------------------------------------------------------
// Kernel 3: edge MLP + maxpool, f32x2 math. Warp = query, 5 groups x 4 edges.
// ---------------------------------------------------------------------------
__global__ void __launch_bounds__(256) k_mlp(const float* __restrict__ x,
                                             const float* __restrict__ lfr,
                                             const float* __restrict__ W1,
                                             const float* __restrict__ b1,
                                             const float* __restrict__ W2,
                                             const float* __restrict__ b2,
                                             float* __restrict__ outp)
{
    __shared__ float sxd[8][D_];
    __shared__ float slf[8][12];
    __shared__ float srel[8][4][D_];
    __shared__ float srl[8][4][D_];
    __shared__ __align__(16) float sa1[8][4][HID_];

    const int tid = threadIdx.x, lane = tid & 31, w = tid >> 5;
    const int q  = blockIdx.x * 8 + w;
    const int b  = q >> 12;
    const int pt = b*N_ + (q - b*M_) * STRIDE_;

    for (int d = lane; d < D_; d += 32) sxd[w][d] = x[(size_t)pt*D_ + d];
    if (lane < 9) slf[w][lane] = lfr[(size_t)pt*9 + lane];
    __syncwarp();

    const int c4 = lane * 4;
    u64_t base01, base23;
    {
        float4 bv = *(const float4*)(b1 + c4);
        base01 = pack2_(bv.x, bv.y);
        base23 = pack2_(bv.z, bv.w);
    }
#pragma unroll 8
    for (int d = 0; d < D_; d++) {
        u64_t xp = pack2_(sxd[w][d], sxd[w][d]);
        ulonglong2 w2 = __ldg((const ulonglong2*)(W1 + d*HID_ + c4));
        base01 = fma2_(xp, w2.x, base01);
        base23 = fma2_(xp, w2.y, base23);
    }
    u64_t b2_01, b2_23;
    {
        float4 bv = __ldg((const float4*)(b2 + c4));
        b2_01 = pack2_(bv.x, bv.y);
        b2_23 = pack2_(bv.z, bv.w);
    }
    float4 mx = make_float4(-CUDART_INF_F, -CUDART_INF_F, -CUDART_INF_F, -CUDART_INF_F);

    for (int grp = 0; grp < 5; grp++) {
        __syncwarp();
        int s = 0;
        if (lane < 4) s = g_nbr[q*K_ + grp*4 + lane];
        const int ss0 = __shfl_sync(0xffffffffu, s, 0);
        const int ss1 = __shfl_sync(0xffffffffu, s, 1);
        const int ss2 = __shfl_sync(0xffffffffu, s, 2);
        const int ss3 = __shfl_sync(0xffffffffu, s, 3);
        {
            const float* xs0 = x + (size_t)ss0 * D_;
            const float* xs1 = x + (size_t)ss1 * D_;
            const float* xs2 = x + (size_t)ss2 * D_;
            const float* xs3 = x + (size_t)ss3 * D_;
#pragma unroll
            for (int d = lane; d < D_; d += 32) {
                float xd = sxd[w][d];
                srel[w][0][d] = xs0[d] - xd;
                srel[w][1][d] = xs1[d] - xd;
                srel[w][2][d] = xs2[d] - xd;
                srel[w][3][d] = xs3[d] - xd;
            }
        }
        __syncwarp();
        // rotate rel -> rel_local with R = lf_dst
#pragma unroll
        for (int t = 0; t < 8; t++) {
            int item = lane + 32*t;
            int e = item >> 6;
            int d = item & 63;
            float v;
            if (d < 16) v = srel[w][e][d];
            else {
                int dd = d - 16;
                int a  = dd % 3;
                int vb = 16 + dd - a;
                v = slf[w][a*3+0]*srel[w][e][vb]
                  + slf[w][a*3+1]*srel[w][e][vb+1]
                  + slf[w][a*3+2]*srel[w][e][vb+2];
            }
            srl[w][e][d] = v;
        }
        __syncwarp();

        u64_t a01[4] = {0,0,0,0}, a23[4] = {0,0,0,0};
#pragma unroll 4
        for (int d = 0; d < D_; d++) {
            ulonglong2 w2 = __ldg((const ulonglong2*)(W1 + (D_+d)*HID_ + c4));
#pragma unroll
            for (int e = 0; e < 4; e++) {
                float r = srl[w][e][d];
                u64_t rp = pack2_(r, r);
                a01[e] = fma2_(rp, w2.x, a01[e]);
                a23[e] = fma2_(rp, w2.y, a23[e]);
            }
        }
#pragma unroll
        for (int e = 0; e < 4; e++) {
            float2 s01 = unpk2_(add2_(base01, a01[e]));
            float2 s23 = unpk2_(add2_(base23, a23[e]));
            float4 st = make_float4(fmaxf(s01.x, 0.f), fmaxf(s01.y, 0.f),
                                    fmaxf(s23.x, 0.f), fmaxf(s23.y, 0.f));
            *(float4*)&sa1[w][e][c4] = st;
        }
        __syncwarp();

        u64_t m01[4] = {b2_01, b2_01, b2_01, b2_01};
        u64_t m23[4] = {b2_23, b2_23, b2_23, b2_23};
#pragma unroll 4
        for (int j = 0; j < HID_; j++) {
            ulonglong2 w2 = __ldg((const ulonglong2*)(W2 + j*HID_ + c4));
#pragma unroll
            for (int e = 0; e < 4; e++) {
                float a = sa1[w][e][j];
                u64_t ap = pack2_(a, a);
                m01[e] = fma2_(ap, w2.x, m01[e]);
                m23[e] = fma2_(ap, w2.y, m23[e]);
            }
        }
#pragma unroll
        for (int e = 0; e < 4; e++) {
            float2 v01 = unpk2_(m01[e]);
            float2 v23 = unpk2_(m23[e]);
            mx.x = fmaxf(mx.x, v01.x);
            mx.y = fmaxf(mx.y, v01.y);
            mx.z = fmaxf(mx.z, v23.x);
            mx.w = fmaxf(mx.w, v23.y);
        }
    }

    *(float4*)(outp + (size_t)q*OUT_ + c4) = mx;
}

// ---------------------------------------------------------------------------
extern "C" void kernel_launch(void* const* d_in, const int* in_sizes, int n_in,
                              void* d_out, int out_size)
{
    const float* x   = (const float*)d_in[0];
    const float* pos = (const float*)d_in[1];
    const float* lfr = (const float*)d_in[2];
    const float* W1  = (const float*)d_in[4];
    const float* b1  = (const float*)d_in[5];
    const float* W2  = (const float*)d_in[6];
    const float* b2  = (const float*)d_in[7];
    float* outp = (float*)d_out;

    const int knn_smem = (2*TK_*KFS_ + 2*TK_ + QB_*KFS_) * (int)sizeof(float); // 105472 B
    cudaFuncSetAttribute(k_knn, cudaFuncAttributeMaxDynamicSharedMemorySize, knn_smem);

    k_prep<<<(B_*N_ + 255)/256, 256>>>(x, pos, lfr, outp, out_size);
    k_knn<<<NQ_/QB_, KNT_, knn_smem>>>();
    k_mlp<<<NQ_/8, 256>>>(x, lfr, W1, b1, W2, b2, outp);
}